// round 16
// baseline (speedup 1.0000x reference)
#include <cuda_runtime.h>
#include <cuda_fp16.h>
#include <math.h>

#define N_NODES  50000
#define N_EDGES  800000
#define NODE_DIM 64
#define EDGE_DIM 32
#define HID      128
#define EPG      16            // edges per warp group (one m16 MMA tile)
#define TPB      256
#define WPB      (TPB / 32)
#define NB       8192          // table bins over d in [0,15], nearest-neighbor
#define TB_BINS  8

typedef unsigned long long ull;

// Per-node packed fp16 rows (see k_node)
__device__ __half g_Ah[(size_t)N_NODES * 512];
// Folded edge-path weights (used only to build the table)
__device__ float g_Mn[32 * 128];
__device__ float g_Mc[32 * 128];
__device__ float g_bn[128];
__device__ float g_bc[128];
// Packed fp16 table, 256 halves per bin
__device__ __half g_Th[(size_t)(NB + 1) * 256];
// dst-sort scratch
__device__ int g_cnt[N_NODES];
__device__ int g_cur[N_NODES];
__device__ int g_ord[N_EDGES];

union F4 { float4 f; ulonglong2 u; };

__device__ __forceinline__ ull pk2(float x, float y) {
    ull r; asm("mov.b64 %0,{%1,%2};" : "=l"(r) : "f"(x), "f"(y)); return r;
}
__device__ __forceinline__ void upk2(ull v, float& x, float& y) {
    asm("mov.b64 {%0,%1},%2;" : "=f"(x), "=f"(y) : "l"(v));
}
__device__ __forceinline__ ull fadd2(ull a, ull b) {
    ull d; asm("add.rn.f32x2 %0,%1,%2;" : "=l"(d) : "l"(a), "l"(b)); return d;
}
__device__ __forceinline__ ull h2f2(unsigned int h) {
    ull r;
    asm("{\n\t"
        ".reg .f16 a,b;\n\t"
        ".reg .f32 lo,hi;\n\t"
        "mov.b32 {a,b},%1;\n\t"
        "cvt.f32.f16 lo,a;\n\t"
        "cvt.f32.f16 hi,b;\n\t"
        "mov.b64 %0,{lo,hi};\n\t"
        "}" : "=l"(r) : "r"(h));
    return r;
}
__device__ __forceinline__ float silu1(float z) {
    float hz = 0.5f * z;
    float th;
    asm("tanh.approx.f32 %0, %1;" : "=f"(th) : "f"(hz));
    return fmaf(hz, th, hz);
}
__device__ __forceinline__ unsigned int smem_u32(const void* p) {
    unsigned int a;
    asm("{ .reg .u64 t; cvta.to.shared.u64 t, %1; cvt.u32.u64 %0, t; }" : "=r"(a) : "l"(p));
    return a;
}

// ---------------------------------------------------------------------------
// K0: fold edge-path weights
// ---------------------------------------------------------------------------
__global__ void k_fold(const float* __restrict__ We2, const float* __restrict__ be2,
                       const float* __restrict__ Wn1, const float* __restrict__ bn1,
                       const float* __restrict__ Wc1, const float* __restrict__ bc1) {
    int j = threadIdx.x;
    float bn = bn1[j], bc = bc1[j];
    for (int b = 0; b < 32; b++) {
        bn += be2[b] * Wn1[(128 + b) * 128 + j];
        bc += be2[b] * Wc1[(128 + b) * 128 + j];
    }
    g_bn[j] = bn;
    g_bc[j] = bc;
    for (int a = 0; a < 32; a++) {
        float sn = 0.f, sc = 0.f;
        for (int b = 0; b < 32; b++) {
            float w = We2[a * 32 + b];
            sn += w * Wn1[(128 + b) * 128 + j];
            sc += w * Wc1[(128 + b) * 128 + j];
        }
        g_Mn[a * 128 + j] = sn;
        g_Mc[a * 128 + j] = sc;
    }
}

// ---------------------------------------------------------------------------
// K0b: build packed fp16 edge-path table.
// ---------------------------------------------------------------------------
__global__ void k_tab(const float* __restrict__ We1, const float* __restrict__ be1) {
    __shared__ float M_sh[8192];
    __shared__ float b_sh[256];
    __shared__ float t_sh[32];
    int j = threadIdx.x;
    for (int i = j; i < 4096; i += 256) {
        M_sh[i]        = g_Mn[i];
        M_sh[4096 + i] = g_Mc[i];
    }
    if (j < 128) {
        b_sh[j]       = g_bn[j];
        b_sh[128 + j] = g_bc[j];
    }
    __syncthreads();

    const float* M = (j < 128) ? M_sh : (M_sh + 4096);
    int jj = j & 127;
    float bb = b_sh[j];
    int pos = (jj >> 2) * 8 + (jj & 3) + ((j < 128) ? 0 : 4);

    for (int bi = 0; bi < TB_BINS; bi++) {
        int i = blockIdx.x * TB_BINS + bi;
        if (i > NB) break;
        float d = (15.0f / NB) * i;
        if (j < 32) {
            float z = d * We1[j] + be1[j];
            t_sh[j] = z / (1.f + __expf(-z));
        }
        __syncthreads();
        float s = bb;
#pragma unroll 8
        for (int k = 0; k < 32; k++) s += t_sh[k] * M[k * 128 + jj];
        g_Th[(size_t)i * 256 + pos] = __float2half_rn(s);
        __syncthreads();
    }
}

// ---------------------------------------------------------------------------
// K1: per-node precompute, packed fp16 output.
// ---------------------------------------------------------------------------
#define NPB 16
__global__ void k_node(const float* __restrict__ h,
                       const float* __restrict__ Wn1,
                       const float* __restrict__ Wc1) {
    __shared__ ull h2[NPB * 64];
    int node0 = blockIdx.x * NPB;
    for (int i = threadIdx.x; i < NPB * 64; i += 128) {
        float hv = h[node0 * 64 + i];
        h2[i] = pk2(hv, hv);
    }
    __syncthreads();
    int j = threadIdx.x;
    int m = j >> 5;
    int c = (j & 31) * 4;
    const float* W = ((m & 2) ? Wc1 : Wn1) + ((m & 1) ? 64 * 128 : 0);
    int off = ((m & 1) ? 256 : 0) + (j & 31) * 8 + ((m & 2) ? 4 : 0);

    ull a0[NPB], a1[NPB];
#pragma unroll
    for (int n = 0; n < NPB; n++) { a0[n] = 0ull; a1[n] = 0ull; }
#pragma unroll 4
    for (int k = 0; k < 64; k++) {
        F4 w; w.f = *(const float4*)&W[k * 128 + c];
#pragma unroll
        for (int n = 0; n < NPB; n++) {
            ull hv = h2[n * 64 + k];
            asm("fma.rn.f32x2 %0,%1,%2,%0;" : "+l"(a0[n]) : "l"(hv), "l"(w.u.x));
            asm("fma.rn.f32x2 %0,%1,%2,%0;" : "+l"(a1[n]) : "l"(hv), "l"(w.u.y));
        }
    }
#pragma unroll
    for (int n = 0; n < NPB; n++) {
        float x0, x1, x2, x3;
        upk2(a0[n], x0, x1);
        upk2(a1[n], x2, x3);
        __half2 hA = __float22half2_rn(make_float2(x0, x1));
        __half2 hB = __float22half2_rn(make_float2(x2, x3));
        uint2 st;
        st.x = *(unsigned int*)&hA;
        st.y = *(unsigned int*)&hB;
        *(uint2*)&g_Ah[(size_t)(node0 + n) * 512 + off] = st;
    }
}

// ---------------------------------------------------------------------------
// K2: initialize output with (h, x)
// ---------------------------------------------------------------------------
__global__ void k_init(const float4* __restrict__ h4, const float4* __restrict__ x4,
                       float4* __restrict__ out4) {
    const int nh4  = N_NODES * 16;
    const int tot4 = nh4 + N_NODES * 3 / 4;
    for (int i = blockIdx.x * blockDim.x + threadIdx.x; i < tot4; i += gridDim.x * blockDim.x)
        out4[i] = (i < nh4) ? h4[i] : x4[i - nh4];
}

// ---------------------------------------------------------------------------
// Sort-by-dst build: zero, histogram, scan, permutation
// ---------------------------------------------------------------------------
__global__ void k_zero() {
    int i = blockIdx.x * blockDim.x + threadIdx.x;
    if (i < N_NODES) g_cnt[i] = 0;
}
__global__ void k_hist(const int* __restrict__ eidx) {
    for (int e = blockIdx.x * blockDim.x + threadIdx.x; e < N_EDGES;
         e += gridDim.x * blockDim.x)
        atomicAdd(&g_cnt[eidx[N_EDGES + e]], 1);
}
__global__ void k_scan() {
    __shared__ int sh[1024];
    __shared__ int carry_sh;
    if (threadIdx.x == 0) carry_sh = 0;
    __syncthreads();
    for (int b = 0; b < N_NODES; b += 1024) {
        int i = b + threadIdx.x;
        int v = (i < N_NODES) ? g_cnt[i] : 0;
        sh[threadIdx.x] = v;
        __syncthreads();
        for (int st = 1; st < 1024; st <<= 1) {
            int t = (threadIdx.x >= st) ? sh[threadIdx.x - st] : 0;
            __syncthreads();
            sh[threadIdx.x] += t;
            __syncthreads();
        }
        int carry = carry_sh;
        if (i < N_NODES) g_cur[i] = carry + sh[threadIdx.x] - v;
        __syncthreads();
        if (threadIdx.x == 0) carry_sh = carry + sh[1023];
        __syncthreads();
    }
}
__global__ void k_perm(const int* __restrict__ eidx) {
    for (int e = blockIdx.x * blockDim.x + threadIdx.x; e < N_EDGES;
         e += gridDim.x * blockDim.x) {
        int d = eidx[N_EDGES + e];
        int p = atomicAdd(&g_cur[d], 1);
        g_ord[p] = e;
    }
}

// ---------------------------------------------------------------------------
// K3: edge kernel. Sorted order; HMMA phase 2; segmented-aggregated scatter.
// ---------------------------------------------------------------------------
#define BT_H  (64 * 136)            // 8704 halves
#define AW_H  (16 * 136)            // 2176 halves per warp (4352 B = 16*68 floats)
#define SMEM_BYTES (2 * (BT_H + WPB * AW_H) + 128 * 4 + 64 * 4 + WPB * 16 * 4)

__global__ void __launch_bounds__(TPB, 2)
k_edge(const float* __restrict__ dist,
       const int*   __restrict__ eidx,
       const float* __restrict__ x,
       const float* __restrict__ bn2,
       const float* __restrict__ Wc2,
       const float* __restrict__ Wn2,
       float* __restrict__ out) {
    extern __shared__ __half smh[];
    __half* Bt_sh = smh;                       // [64][136] = Wn2^T fp16
    __half* A_all = smh + BT_H;
    float*  Wc2_sh = (float*)(smh + BT_H + WPB * AW_H);
    float*  bn2_sh = Wc2_sh + 128;
    int*    dst_all = (int*)(bn2_sh + 64);     // WPB*16

    for (int idx = threadIdx.x; idx < 8192; idx += TPB) {
        int n = idx >> 7, k = idx & 127;
        Bt_sh[n * 136 + k] = __float2half_rn(Wn2[k * 64 + n]);
    }
    if (threadIdx.x < 128) Wc2_sh[threadIdx.x] = Wc2[threadIdx.x];
    if (threadIdx.x < 64)  bn2_sh[threadIdx.x] = bn2[threadIdx.x];
    __syncthreads();

    const int lane = threadIdx.x & 31;
    const int wib  = threadIdx.x >> 5;
    const int gw   = blockIdx.x * WPB + wib;
    const int nw   = gridDim.x * WPB;

    F4 wc2_4; wc2_4.f = *(const float4*)&Wc2_sh[4 * lane];
    float2 bn2p[8];
#pragma unroll
    for (int nt = 0; nt < 8; nt++)
        bn2p[nt] = *(const float2*)&bn2_sh[nt * 8 + 2 * (lane & 3)];

    __half* A_w = A_all + wib * AW_H;
    float*  mst = (float*)A_w;                 // staging reuses A tile (16*68 floats)
    int*    dst_sh = dst_all + wib * 16;
    const unsigned int A_base  = smem_u32(A_w);
    const unsigned int Bt_base = smem_u32(Bt_sh);
    const unsigned int a_sel = A_base + (lane & 15) * 272 + (lane >> 4) * 16;
    const int t16 = lane & 15;
    const unsigned int b_sel = Bt_base + (t16 & 7) * 272 + (t16 >> 3) * 16;

    const uint4* A4h = (const uint4*)g_Ah;
    const uint4* T4h = (const uint4*)g_Th;
    float* out_x = out + (size_t)N_NODES * 64;
    const int myc = 2 * lane;

    for (int base = gw * EPG; base < N_EDGES; base += nw * EPG) {

        // ---- phase 1: two 8-edge halves (sorted order), gn stored fp16 ----
#pragma unroll 1
        for (int hf = 0; hf < 2; hf++) {
            int src8[8], dst8[8];
            float cw[8];
#pragma unroll
            for (int ee = 0; ee < 8; ee++) {
                int e = g_ord[base + hf * 8 + ee];
                float d = dist[e];
                int s  = eidx[e];
                int dd = eidx[N_EDGES + e];
                src8[ee] = s; dst8[ee] = dd;
                if (lane == 0) dst_sh[hf * 8 + ee] = dd;

                float p = d * (NB / 15.0f) + 0.5f;
                int i0 = (int)p;
                i0 = max(0, min(i0, NB));

                uint4 sv = A4h[(size_t)s  * 64 + lane];
                uint4 dv = A4h[(size_t)dd * 64 + 32 + lane];
                uint4 tv = T4h[(size_t)i0 * 32 + lane];

                // node-MLP hidden -> silu -> fp16 A tile
                {
                    ull px = fadd2(fadd2(h2f2(sv.x), h2f2(dv.x)), h2f2(tv.x));
                    ull py = fadd2(fadd2(h2f2(sv.y), h2f2(dv.y)), h2f2(tv.y));
                    float p0, p1, p2, p3;
                    upk2(px, p0, p1);
                    upk2(py, p2, p3);
                    __half2 h0 = __float22half2_rn(make_float2(silu1(p0), silu1(p1)));
                    __half2 h1 = __float22half2_rn(make_float2(silu1(p2), silu1(p3)));
                    uint2 st;
                    st.x = *(unsigned int*)&h0;
                    st.y = *(unsigned int*)&h1;
                    *(uint2*)&A_w[(hf * 8 + ee) * 136 + lane * 4] = st;
                }
                // coord-MLP hidden -> scalar cw
                {
                    ull px = fadd2(fadd2(h2f2(sv.z), h2f2(dv.z)), h2f2(tv.z));
                    ull py = fadd2(fadd2(h2f2(sv.w), h2f2(dv.w)), h2f2(tv.w));
                    float p0, p1, p2, p3;
                    upk2(px, p0, p1);
                    upk2(py, p2, p3);
                    float ss = silu1(p0) * wc2_4.f.x + silu1(p1) * wc2_4.f.y
                             + silu1(p2) * wc2_4.f.z + silu1(p3) * wc2_4.f.w;
#pragma unroll
                    for (int off = 16; off > 0; off >>= 1)
                        ss += __shfl_xor_sync(0xffffffffu, ss, off);
                    cw[ee] = ss;
                }
            }

            // coord scatter (lanes 0..7)
            if (lane < 8) {
                float mycw = cw[0]; int ms = src8[0], md = dst8[0];
#pragma unroll
                for (int ee = 1; ee < 8; ee++)
                    if (lane == ee) { mycw = cw[ee]; ms = src8[ee]; md = dst8[ee]; }
                float dx = x[ms * 3 + 0] - x[md * 3 + 0];
                float dy = x[ms * 3 + 1] - x[md * 3 + 1];
                float dz = x[ms * 3 + 2] - x[md * 3 + 2];
                float len = fmaxf(sqrtf(dx * dx + dy * dy + dz * dz), 1e-8f);
                float inv = mycw / len;
                float* ox = out_x + (size_t)md * 3;
                atomicAdd(&ox[0], dx * inv);
                atomicAdd(&ox[1], dy * inv);
                atomicAdd(&ox[2], dz * inv);
            }
        }
        __syncwarp();   // A stores + dst_sh visible

        // ---- phase 2: m16 x n64 x k128 HMMA ----
        float c0[8], c1[8], c2[8], c3[8];
#pragma unroll
        for (int nt = 0; nt < 8; nt++) {
            c0[nt] = bn2p[nt].x; c1[nt] = bn2p[nt].y;
            c2[nt] = bn2p[nt].x; c3[nt] = bn2p[nt].y;
        }
#pragma unroll
        for (int ks = 0; ks < 8; ks++) {
            unsigned int a0, a1, a2, a3;
            asm volatile("ldmatrix.sync.aligned.m8n8.x4.shared.b16 {%0,%1,%2,%3}, [%4];"
                         : "=r"(a0), "=r"(a1), "=r"(a2), "=r"(a3)
                         : "r"(a_sel + ks * 32));
#pragma unroll
            for (int nt = 0; nt < 8; nt++) {
                unsigned int b0, b1;
                asm volatile("ldmatrix.sync.aligned.m8n8.x2.shared.b16 {%0,%1}, [%2];"
                             : "=r"(b0), "=r"(b1)
                             : "r"(b_sel + nt * 2176 + ks * 32));
                asm volatile("mma.sync.aligned.m16n8k16.row.col.f32.f16.f16.f32 "
                             "{%0,%1,%2,%3}, {%4,%5,%6,%7}, {%8,%9}, {%0,%1,%2,%3};"
                             : "+f"(c0[nt]), "+f"(c1[nt]), "+f"(c2[nt]), "+f"(c3[nt])
                             : "r"(a0), "r"(a1), "r"(a2), "r"(a3), "r"(b0), "r"(b1));
            }
        }
        __syncwarp();   // ldmatrix reads done before staging overwrites A tile

        // ---- stage C to smem: m[16][68] fp32 (reuses A tile bytes) ----
        {
            int row0 = lane >> 2;
            int col  = 2 * (lane & 3);
#pragma unroll
            for (int nt = 0; nt < 8; nt++) {
                mst[row0 * 68 + 8 * nt + col]           = c0[nt];
                mst[row0 * 68 + 8 * nt + col + 1]       = c1[nt];
                mst[(row0 + 8) * 68 + 8 * nt + col]     = c2[nt];
                mst[(row0 + 8) * 68 + 8 * nt + col + 1] = c3[nt];
            }
        }
        __syncwarp();

        // ---- segmented aggregation over sorted rows, then few atomics ----
        {
            int prevd = dst_sh[0];
            float acc0 = mst[myc], acc1 = mst[myc + 1];
#pragma unroll 1
            for (int r = 1; r < 16; r++) {
                int d = dst_sh[r];
                float v0 = mst[r * 68 + myc], v1 = mst[r * 68 + myc + 1];
                if (d != prevd) {
                    atomicAdd(&out[(size_t)prevd * 64 + myc],     acc0);
                    atomicAdd(&out[(size_t)prevd * 64 + myc + 1], acc1);
                    acc0 = v0; acc1 = v1; prevd = d;
                } else {
                    acc0 += v0; acc1 += v1;
                }
            }
            atomicAdd(&out[(size_t)prevd * 64 + myc],     acc0);
            atomicAdd(&out[(size_t)prevd * 64 + myc + 1], acc1);
        }
        __syncwarp();   // staging reuse safety
    }
}

// ---------------------------------------------------------------------------
extern "C" void kernel_launch(void* const* d_in, const int* in_sizes, int n_in,
                              void* d_out, int out_size) {
    const float* h    = (const float*)d_in[0];
    const float* x    = (const float*)d_in[1];
    const float* dist = (const float*)d_in[2];
    const float* We1  = (const float*)d_in[3];
    const float* be1  = (const float*)d_in[4];
    const float* We2  = (const float*)d_in[5];
    const float* be2  = (const float*)d_in[6];
    const float* Wn1  = (const float*)d_in[7];
    const float* bn1  = (const float*)d_in[8];
    const float* Wn2  = (const float*)d_in[9];
    const float* bn2  = (const float*)d_in[10];
    const float* Wc1  = (const float*)d_in[11];
    const float* bc1  = (const float*)d_in[12];
    const float* Wc2  = (const float*)d_in[13];
    const int*   eidx = (const int*)d_in[14];
    float* out = (float*)d_out;

    static bool attr_set = false;
    if (!attr_set) {
        cudaFuncSetAttribute(k_edge, cudaFuncAttributeMaxDynamicSharedMemorySize, 56 * 1024);
        attr_set = true;
    }

    k_fold<<<1, 128>>>(We2, be2, Wn1, bn1, Wc1, bc1);
    k_tab<<<(NB + 1 + TB_BINS - 1) / TB_BINS, 256>>>(We1, be1);
    k_node<<<N_NODES / NPB, 128>>>(h, Wn1, Wc1);
    k_init<<<1024, 256>>>((const float4*)h, (const float4*)x, (float4*)out);

    // dst sort build
    k_zero<<<(N_NODES + 255) / 256, 256>>>();
    k_hist<<<592, 256>>>(eidx);
    k_scan<<<1, 1024>>>();
    k_perm<<<592, 256>>>(eidx);

    k_edge<<<296, TPB, SMEM_BYTES>>>(dist, eidx, x, bn2, Wc2, Wn2, out);
}

// round 17
// speedup vs baseline: 1.2110x; 1.2110x over previous
#include <cuda_runtime.h>
#include <cuda_fp16.h>
#include <math.h>

#define N_NODES  50000
#define N_EDGES  800000
#define NODE_DIM 64
#define EDGE_DIM 32
#define HID      128
#define EPG      16            // edges per warp group (one m16 MMA tile)
#define TPB      256
#define WPB      (TPB / 32)
#define NB       8192          // table bins over d in [0,15], nearest-neighbor
#define TB_BINS  8

typedef unsigned long long ull;

// Per-node packed fp16 rows (see pos() mapping in k_node)
__device__ __half g_Ah[(size_t)N_NODES * 512];
// Folded edge-path weights (used only to build the table)
__device__ float g_Mn[32 * 128];
__device__ float g_Mc[32 * 128];
__device__ float g_bn[128];
__device__ float g_bc[128];
// Packed fp16 table, 256 halves per bin
__device__ __half g_Th[(size_t)(NB + 1) * 256];

union F4 { float4 f; ulonglong2 u; };

__device__ __forceinline__ ull pk2(float x, float y) {
    ull r; asm("mov.b64 %0,{%1,%2};" : "=l"(r) : "f"(x), "f"(y)); return r;
}
__device__ __forceinline__ void upk2(ull v, float& x, float& y) {
    asm("mov.b64 {%0,%1},%2;" : "=f"(x), "=f"(y) : "l"(v));
}
__device__ __forceinline__ ull fadd2(ull a, ull b) {
    ull d; asm("add.rn.f32x2 %0,%1,%2;" : "=l"(d) : "l"(a), "l"(b)); return d;
}
__device__ __forceinline__ ull h2f2(unsigned int h) {
    ull r;
    asm("{\n\t"
        ".reg .f16 a,b;\n\t"
        ".reg .f32 lo,hi;\n\t"
        "mov.b32 {a,b},%1;\n\t"
        "cvt.f32.f16 lo,a;\n\t"
        "cvt.f32.f16 hi,b;\n\t"
        "mov.b64 %0,{lo,hi};\n\t"
        "}" : "=l"(r) : "r"(h));
    return r;
}
__device__ __forceinline__ float silu1(float z) {
    float hz = 0.5f * z;
    float th;
    asm("tanh.approx.f32 %0, %1;" : "=f"(th) : "f"(hz));
    return fmaf(hz, th, hz);
}
__device__ __forceinline__ unsigned int smem_u32(const void* p) {
    unsigned int a;
    asm("{ .reg .u64 t; cvta.to.shared.u64 t, %1; cvt.u32.u64 %0, t; }" : "=r"(a) : "l"(p));
    return a;
}

// ---------------------------------------------------------------------------
// K0: fold edge-path weights
// ---------------------------------------------------------------------------
__global__ void k_fold(const float* __restrict__ We2, const float* __restrict__ be2,
                       const float* __restrict__ Wn1, const float* __restrict__ bn1,
                       const float* __restrict__ Wc1, const float* __restrict__ bc1) {
    int j = threadIdx.x;
    float bn = bn1[j], bc = bc1[j];
    for (int b = 0; b < 32; b++) {
        bn += be2[b] * Wn1[(128 + b) * 128 + j];
        bc += be2[b] * Wc1[(128 + b) * 128 + j];
    }
    g_bn[j] = bn;
    g_bc[j] = bc;
    for (int a = 0; a < 32; a++) {
        float sn = 0.f, sc = 0.f;
        for (int b = 0; b < 32; b++) {
            float w = We2[a * 32 + b];
            sn += w * Wn1[(128 + b) * 128 + j];
            sc += w * Wc1[(128 + b) * 128 + j];
        }
        g_Mn[a * 128 + j] = sn;
        g_Mc[a * 128 + j] = sc;
    }
}

// ---------------------------------------------------------------------------
// K0b: build packed fp16 edge-path table.
// ---------------------------------------------------------------------------
__global__ void k_tab(const float* __restrict__ We1, const float* __restrict__ be1) {
    __shared__ float M_sh[8192];
    __shared__ float b_sh[256];
    __shared__ float t_sh[32];
    int j = threadIdx.x;
    for (int i = j; i < 4096; i += 256) {
        M_sh[i]        = g_Mn[i];
        M_sh[4096 + i] = g_Mc[i];
    }
    if (j < 128) {
        b_sh[j]       = g_bn[j];
        b_sh[128 + j] = g_bc[j];
    }
    __syncthreads();

    const float* M = (j < 128) ? M_sh : (M_sh + 4096);
    int jj = j & 127;
    float bb = b_sh[j];
    int pos = (jj >> 2) * 8 + (jj & 3) + ((j < 128) ? 0 : 4);

    for (int bi = 0; bi < TB_BINS; bi++) {
        int i = blockIdx.x * TB_BINS + bi;
        if (i > NB) break;
        float d = (15.0f / NB) * i;
        if (j < 32) {
            float z = d * We1[j] + be1[j];
            t_sh[j] = z / (1.f + __expf(-z));
        }
        __syncthreads();
        float s = bb;
#pragma unroll 8
        for (int k = 0; k < 32; k++) s += t_sh[k] * M[k * 128 + jj];
        g_Th[(size_t)i * 256 + pos] = __float2half_rn(s);
        __syncthreads();
    }
}

// ---------------------------------------------------------------------------
// K1: per-node precompute via HMMA. 128 nodes/block, 8 warps.
//   A = h[50000x64] @ Wbig[64x512], Wbig cols: [Wn1_src|Wn1_dst|Wc1_src|Wc1_dst]
//   Output stored fp16 in the packed g_Ah layout.
// smem: Bt[512][72] fp16 (Wbig^T) + At[128][72] fp16 (h tile)
// ---------------------------------------------------------------------------
#define KN_SMEM ((512 * 72 + 128 * 72) * 2)

__global__ void __launch_bounds__(256, 2)
k_node(const float* __restrict__ h,
       const float* __restrict__ Wn1,
       const float* __restrict__ Wc1) {
    extern __shared__ __half knsm[];
    __half* Bt = knsm;                 // [512][72]: Bt[j][k] = Wbig[k][j]
    __half* At = knsm + 512 * 72;      // [128][72]: At[n][k] = h[n0+n][k]

    int n0 = blockIdx.x * 128;
    for (int idx = threadIdx.x; idx < 512 * 64; idx += 256) {
        int j = idx >> 6, k = idx & 63;
        const float* W = (j < 256) ? Wn1 : Wc1;
        int jj = j & 255;
        int row = (jj < 128) ? k : (64 + k);
        int col = jj & 127;
        Bt[j * 72 + k] = __float2half_rn(W[row * 128 + col]);
    }
    for (int idx = threadIdx.x; idx < 128 * 64; idx += 256) {
        int n = idx >> 6, k = idx & 63;
        int node = n0 + n;
        float hv = (node < N_NODES) ? h[node * 64 + k] : 0.f;
        At[n * 72 + k] = __float2half_rn(hv);
    }
    __syncthreads();

    int lane = threadIdx.x & 31;
    int wib  = threadIdx.x >> 5;
    const __half* Aw = At + wib * 16 * 72;
    unsigned int a_sel = smem_u32(Aw) + (lane & 15) * 144 + (lane >> 4) * 16;
    int t16 = lane & 15;
    unsigned int b0_sel = smem_u32(Bt) + (t16 & 7) * 144 + (t16 >> 3) * 16;

    int nodeA = n0 + wib * 16 + (lane >> 2);
    int nodeB = nodeA + 8;
    int cb = 2 * (lane & 3);

#pragma unroll 1
    for (int ch = 0; ch < 8; ch++) {
        float c0[8], c1[8], c2[8], c3[8];
#pragma unroll
        for (int nt = 0; nt < 8; nt++) { c0[nt] = 0.f; c1[nt] = 0.f; c2[nt] = 0.f; c3[nt] = 0.f; }
#pragma unroll
        for (int ks = 0; ks < 4; ks++) {
            unsigned int a0, a1, a2, a3;
            asm volatile("ldmatrix.sync.aligned.m8n8.x4.shared.b16 {%0,%1,%2,%3}, [%4];"
                         : "=r"(a0), "=r"(a1), "=r"(a2), "=r"(a3)
                         : "r"(a_sel + ks * 32));
#pragma unroll
            for (int nt = 0; nt < 8; nt++) {
                unsigned int b0, b1;
                asm volatile("ldmatrix.sync.aligned.m8n8.x2.shared.b16 {%0,%1}, [%2];"
                             : "=r"(b0), "=r"(b1)
                             : "r"(b0_sel + (ch * 64 + nt * 8) * 144 + ks * 32));
                asm volatile("mma.sync.aligned.m16n8k16.row.col.f32.f16.f16.f32 "
                             "{%0,%1,%2,%3}, {%4,%5,%6,%7}, {%8,%9}, {%0,%1,%2,%3};"
                             : "+f"(c0[nt]), "+f"(c1[nt]), "+f"(c2[nt]), "+f"(c3[nt])
                             : "r"(a0), "r"(a1), "r"(a2), "r"(a3), "r"(b0), "r"(b1));
            }
        }
        // store: lane owns rows lane/4, lane/4+8; cols ch*64+nt*8+cb, +1
#pragma unroll
        for (int nt = 0; nt < 8; nt++) {
            int j = ch * 64 + nt * 8 + cb;
            int m = j >> 7, c = j & 127;
            int off = ((m & 1) ? 256 : 0) + (c >> 2) * 8 + ((m & 2) ? 4 : 0) + (c & 3);
            if (nodeA < N_NODES) {
                __half2 v = __float22half2_rn(make_float2(c0[nt], c1[nt]));
                *(unsigned int*)&g_Ah[(size_t)nodeA * 512 + off] = *(unsigned int*)&v;
            }
            if (nodeB < N_NODES) {
                __half2 v = __float22half2_rn(make_float2(c2[nt], c3[nt]));
                *(unsigned int*)&g_Ah[(size_t)nodeB * 512 + off] = *(unsigned int*)&v;
            }
        }
    }
}

// ---------------------------------------------------------------------------
// K2: initialize output with (h, x)
// ---------------------------------------------------------------------------
__global__ void k_init(const float4* __restrict__ h4, const float4* __restrict__ x4,
                       float4* __restrict__ out4) {
    const int nh4  = N_NODES * 16;
    const int tot4 = nh4 + N_NODES * 3 / 4;
    for (int i = blockIdx.x * blockDim.x + threadIdx.x; i < tot4; i += gridDim.x * blockDim.x)
        out4[i] = (i < nh4) ? h4[i] : x4[i - nh4];
}

// ---------------------------------------------------------------------------
// K3: edge kernel (round-15 champion). Phase1: gathers+silu -> fp16 tile.
// Phase2: m16n64k128 HMMA. Direct edge order, scalar-atomic scatter.
// ---------------------------------------------------------------------------
#define BT_H  (64 * 136)            // 8704 halves
#define AW_H  (16 * 136)            // 2176 halves per warp
#define SMEM_BYTES (2 * (BT_H + WPB * AW_H) + 128 * 4 + 64 * 4)

__global__ void __launch_bounds__(TPB, 2)
k_edge(const float* __restrict__ dist,
       const int*   __restrict__ eidx,
       const float* __restrict__ x,
       const float* __restrict__ bn2,
       const float* __restrict__ Wc2,
       const float* __restrict__ Wn2,
       float* __restrict__ out) {
    extern __shared__ __half smh[];
    __half* Bt_sh = smh;                       // [64][136] = Wn2^T fp16
    __half* A_all = smh + BT_H;
    float*  Wc2_sh = (float*)(smh + BT_H + WPB * AW_H);
    float*  bn2_sh = Wc2_sh + 128;

    for (int idx = threadIdx.x; idx < 8192; idx += TPB) {
        int n = idx >> 7, k = idx & 127;
        Bt_sh[n * 136 + k] = __float2half_rn(Wn2[k * 64 + n]);
    }
    if (threadIdx.x < 128) Wc2_sh[threadIdx.x] = Wc2[threadIdx.x];
    if (threadIdx.x < 64)  bn2_sh[threadIdx.x] = bn2[threadIdx.x];
    __syncthreads();

    const int lane = threadIdx.x & 31;
    const int wib  = threadIdx.x >> 5;
    const int gw   = blockIdx.x * WPB + wib;
    const int nw   = gridDim.x * WPB;

    F4 wc2_4; wc2_4.f = *(const float4*)&Wc2_sh[4 * lane];
    float2 bn2p[8];
#pragma unroll
    for (int nt = 0; nt < 8; nt++)
        bn2p[nt] = *(const float2*)&bn2_sh[nt * 8 + 2 * (lane & 3)];

    __half* A_w = A_all + wib * AW_H;
    const unsigned int A_base  = smem_u32(A_w);
    const unsigned int Bt_base = smem_u32(Bt_sh);
    const unsigned int a_sel = A_base + (lane & 15) * 272 + (lane >> 4) * 16;
    const int t16 = lane & 15;
    const unsigned int b_sel = Bt_base + (t16 & 7) * 272 + (t16 >> 3) * 16;

    const uint4* A4h = (const uint4*)g_Ah;     // 64 uint4 per node
    const uint4* T4h = (const uint4*)g_Th;     // 32 uint4 per table row
    float* out_x = out + (size_t)N_NODES * 64;

    for (int base = gw * EPG; base < N_EDGES; base += nw * EPG) {

        // ---- phase 1: two 8-edge halves (proven), gn stored fp16 ----
#pragma unroll 1
        for (int hf = 0; hf < 2; hf++) {
            int src8[8], dst8[8];
            float cw[8];
#pragma unroll
            for (int ee = 0; ee < 8; ee++) {
                int e = base + hf * 8 + ee;
                float d = dist[e];
                int s  = eidx[e];
                int dd = eidx[N_EDGES + e];
                src8[ee] = s; dst8[ee] = dd;

                float p = d * (NB / 15.0f) + 0.5f;
                int i0 = (int)p;
                i0 = max(0, min(i0, NB));

                uint4 sv = A4h[(size_t)s  * 64 + lane];
                uint4 dv = A4h[(size_t)dd * 64 + 32 + lane];
                uint4 tv = T4h[(size_t)i0 * 32 + lane];

                // node-MLP hidden -> silu -> fp16 A tile
                {
                    ull px = fadd2(fadd2(h2f2(sv.x), h2f2(dv.x)), h2f2(tv.x));
                    ull py = fadd2(fadd2(h2f2(sv.y), h2f2(dv.y)), h2f2(tv.y));
                    float p0, p1, p2, p3;
                    upk2(px, p0, p1);
                    upk2(py, p2, p3);
                    __half2 h0 = __float22half2_rn(make_float2(silu1(p0), silu1(p1)));
                    __half2 h1 = __float22half2_rn(make_float2(silu1(p2), silu1(p3)));
                    uint2 st;
                    st.x = *(unsigned int*)&h0;
                    st.y = *(unsigned int*)&h1;
                    *(uint2*)&A_w[(hf * 8 + ee) * 136 + lane * 4] = st;
                }
                // coord-MLP hidden -> scalar cw
                {
                    ull px = fadd2(fadd2(h2f2(sv.z), h2f2(dv.z)), h2f2(tv.z));
                    ull py = fadd2(fadd2(h2f2(sv.w), h2f2(dv.w)), h2f2(tv.w));
                    float p0, p1, p2, p3;
                    upk2(px, p0, p1);
                    upk2(py, p2, p3);
                    float ss = silu1(p0) * wc2_4.f.x + silu1(p1) * wc2_4.f.y
                             + silu1(p2) * wc2_4.f.z + silu1(p3) * wc2_4.f.w;
#pragma unroll
                    for (int off = 16; off > 0; off >>= 1)
                        ss += __shfl_xor_sync(0xffffffffu, ss, off);
                    cw[ee] = ss;
                }
            }

            // coord scatter (lanes 0..7)
            if (lane < 8) {
                float mycw = cw[0]; int ms = src8[0], md = dst8[0];
#pragma unroll
                for (int ee = 1; ee < 8; ee++)
                    if (lane == ee) { mycw = cw[ee]; ms = src8[ee]; md = dst8[ee]; }
                float dx = x[ms * 3 + 0] - x[md * 3 + 0];
                float dy = x[ms * 3 + 1] - x[md * 3 + 1];
                float dz = x[ms * 3 + 2] - x[md * 3 + 2];
                float len = fmaxf(sqrtf(dx * dx + dy * dy + dz * dz), 1e-8f);
                float inv = mycw / len;
                float* ox = out_x + (size_t)md * 3;
                atomicAdd(&ox[0], dx * inv);
                atomicAdd(&ox[1], dy * inv);
                atomicAdd(&ox[2], dz * inv);
            }
        }
        __syncwarp();   // all gn stores visible before ldmatrix

        // ---- phase 2: m16 x n64 x k128 HMMA ----
        float c0[8], c1[8], c2[8], c3[8];
#pragma unroll
        for (int nt = 0; nt < 8; nt++) {
            c0[nt] = bn2p[nt].x; c1[nt] = bn2p[nt].y;
            c2[nt] = bn2p[nt].x; c3[nt] = bn2p[nt].y;
        }
#pragma unroll
        for (int ks = 0; ks < 8; ks++) {
            unsigned int a0, a1, a2, a3;
            asm volatile("ldmatrix.sync.aligned.m8n8.x4.shared.b16 {%0,%1,%2,%3}, [%4];"
                         : "=r"(a0), "=r"(a1), "=r"(a2), "=r"(a3)
                         : "r"(a_sel + ks * 32));
#pragma unroll
            for (int nt = 0; nt < 8; nt++) {
                unsigned int b0, b1;
                asm volatile("ldmatrix.sync.aligned.m8n8.x2.shared.b16 {%0,%1}, [%2];"
                             : "=r"(b0), "=r"(b1)
                             : "r"(b_sel + nt * 2176 + ks * 32));
                asm volatile("mma.sync.aligned.m16n8k16.row.col.f32.f16.f16.f32 "
                             "{%0,%1,%2,%3}, {%4,%5,%6,%7}, {%8,%9}, {%0,%1,%2,%3};"
                             : "+f"(c0[nt]), "+f"(c1[nt]), "+f"(c2[nt]), "+f"(c3[nt])
                             : "r"(a0), "r"(a1), "r"(a2), "r"(a3), "r"(b0), "r"(b1));
            }
        }

        // ---- scatter: lane holds rows lane/4, lane/4+8; cols 2*(lane&3),+1 ----
        {
            int e0 = base + (lane >> 2);
            int d0 = eidx[N_EDGES + e0];
            int d1 = eidx[N_EDGES + e0 + 8];
            int coloff = 2 * (lane & 3);
            float* p0 = out + (size_t)d0 * 64 + coloff;
            float* p1 = out + (size_t)d1 * 64 + coloff;
#pragma unroll
            for (int nt = 0; nt < 8; nt++) {
                atomicAdd(p0 + nt * 8,     c0[nt]);
                atomicAdd(p0 + nt * 8 + 1, c1[nt]);
                atomicAdd(p1 + nt * 8,     c2[nt]);
                atomicAdd(p1 + nt * 8 + 1, c3[nt]);
            }
        }
        __syncwarp();   // A tile reuse safety
    }
}

// ---------------------------------------------------------------------------
extern "C" void kernel_launch(void* const* d_in, const int* in_sizes, int n_in,
                              void* d_out, int out_size) {
    const float* h    = (const float*)d_in[0];
    const float* x    = (const float*)d_in[1];
    const float* dist = (const float*)d_in[2];
    const float* We1  = (const float*)d_in[3];
    const float* be1  = (const float*)d_in[4];
    const float* We2  = (const float*)d_in[5];
    const float* be2  = (const float*)d_in[6];
    const float* Wn1  = (const float*)d_in[7];
    const float* bn1  = (const float*)d_in[8];
    const float* Wn2  = (const float*)d_in[9];
    const float* bn2  = (const float*)d_in[10];
    const float* Wc1  = (const float*)d_in[11];
    const float* bc1  = (const float*)d_in[12];
    const float* Wc2  = (const float*)d_in[13];
    const int*   eidx = (const int*)d_in[14];
    float* out = (float*)d_out;

    static bool attr_set = false;
    if (!attr_set) {
        cudaFuncSetAttribute(k_edge, cudaFuncAttributeMaxDynamicSharedMemorySize, 56 * 1024);
        cudaFuncSetAttribute(k_node, cudaFuncAttributeMaxDynamicSharedMemorySize, 96 * 1024);
        attr_set = true;
    }

    k_fold<<<1, 128>>>(We2, be2, Wn1, bn1, Wc1, bc1);
    k_tab<<<(NB + 1 + TB_BINS - 1) / TB_BINS, 256>>>(We1, be1);
    k_node<<<(N_NODES + 127) / 128, 256, KN_SMEM>>>(h, Wn1, Wc1);
    k_init<<<1024, 256>>>((const float4*)h, (const float4*)x, (float4*)out);

    k_edge<<<296, TPB, SMEM_BYTES>>>(dist, eidx, x, bn2, Wc2, Wn2, out);
}